// round 14
// baseline (speedup 1.0000x reference)
#include <cuda_runtime.h>
#include <cuda_fp16.h>
#include <cstdint>

// Problem constants (fixed shapes)
#define B_   2
#define S_   2048
#define D_   1024
#define H_   16
#define HD_  64
#define M_TOT (B_ * S_)   // 4096
#define N3   (3 * D_)     // 3072

// ---------------------------------------------------------------------------
// Scratch buffers (fp16; Q scale folded into Wq/bq; natural layouts)
// ---------------------------------------------------------------------------
__device__ __half g_q[B_ * H_ * S_ * HD_];    // [B,H,S,HD]
__device__ __half g_k[B_ * H_ * S_ * HD_];    // [B,H,S,HD]
__device__ __half g_v[B_ * H_ * S_ * HD_];    // [B,H,S,HD]
__device__ __half g_att[B_ * S_ * D_];        // [B,S,D]
__device__ __half g_xt[M_TOT * D_];           // x fp16 [M,K]
__device__ __half g_wcat[D_ * N3];            // [K, 3N] = [Wq*0.125 | Wk | Wv]
__device__ __half g_wo[D_ * D_];              // Wo fp16 [K,N]
__device__ float  g_bcat[N3];                 // [bq*0.125 | bk | bv]

// ---------------------------------------------------------------------------
// Helpers
// ---------------------------------------------------------------------------
__device__ __forceinline__ void mma_f16(float* d, const unsigned* a,
                                        unsigned b0, unsigned b1) {
    asm volatile(
        "mma.sync.aligned.m16n8k16.row.col.f32.f16.f16.f32 "
        "{%0,%1,%2,%3}, {%4,%5,%6,%7}, {%8,%9}, {%0,%1,%2,%3};"
        : "+f"(d[0]), "+f"(d[1]), "+f"(d[2]), "+f"(d[3])
        : "r"(a[0]), "r"(a[1]), "r"(a[2]), "r"(a[3]), "r"(b0), "r"(b1));
}

__device__ __forceinline__ void cp_async16(void* smem_dst, const void* gmem_src) {
    unsigned saddr = (unsigned)__cvta_generic_to_shared(smem_dst);
    asm volatile("cp.async.cg.shared.global [%0], [%1], 16;"
                 :: "r"(saddr), "l"(gmem_src));
}

__device__ __forceinline__ unsigned pack_h2(float lo, float hi) {
    __half2 h = __floats2half2_rn(lo, hi);
    return *reinterpret_cast<unsigned*>(&h);
}

__device__ __forceinline__ void ldsm_x4(unsigned& d0, unsigned& d1,
                                        unsigned& d2, unsigned& d3,
                                        uint32_t addr) {
    asm volatile("ldmatrix.sync.aligned.m8n8.x4.shared.b16 {%0,%1,%2,%3}, [%4];"
                 : "=r"(d0), "=r"(d1), "=r"(d2), "=r"(d3) : "r"(addr));
}

__device__ __forceinline__ void ldsm_x4_t(unsigned& d0, unsigned& d1,
                                          unsigned& d2, unsigned& d3,
                                          uint32_t addr) {
    asm volatile("ldmatrix.sync.aligned.m8n8.x4.trans.shared.b16 {%0,%1,%2,%3}, [%4];"
                 : "=r"(d0), "=r"(d1), "=r"(d2), "=r"(d3) : "r"(addr));
}

__device__ __forceinline__ uint32_t smem_u32(const void* p) {
    return (uint32_t)__cvta_generic_to_shared(p);
}

// ---------------------------------------------------------------------------
// Prep: x->fp16; Wq*0.125|Wk|Wv -> wcat [K,3N]; Wo->fp16; bcat.
// ---------------------------------------------------------------------------
#define XN4 (M_TOT * D_ / 4)       // 1048576
#define WN4 (D_ * D_ / 4)          // 262144 each

__global__ void __launch_bounds__(256) cvt_all_kernel(
    const float* __restrict__ x,
    const float* __restrict__ wq, const float* __restrict__ wk,
    const float* __restrict__ wv, const float* __restrict__ wo,
    const float* __restrict__ bq, const float* __restrict__ bk,
    const float* __restrict__ bv,
    __half* __restrict__ xt, __half* __restrict__ wcat,
    __half* __restrict__ wot, float* __restrict__ bcat)
{
    int i = blockIdx.x * 256 + threadIdx.x;
    if (i < XN4) {
        float4 v = ((const float4*)x)[i];
        __half2* d = (__half2*)xt + 2 * i;
        d[0] = __floats2half2_rn(v.x, v.y);
        d[1] = __floats2half2_rn(v.z, v.w);
    } else if (i < XN4 + 4 * WN4) {
        int j = i - XN4;
        int w = j >> 18;
        int off = j & (WN4 - 1);
        if (w == 3) {
            float4 v = ((const float4*)wo)[off];
            __half2* d = (__half2*)wot + 2 * off;
            d[0] = __floats2half2_rn(v.x, v.y);
            d[1] = __floats2half2_rn(v.z, v.w);
        } else {
            const float* ws = (w == 0) ? wq : (w == 1) ? wk : wv;
            float sc = (w == 0) ? 0.125f : 1.0f;
            float4 v = ((const float4*)ws)[off];
            int k = (off * 4) >> 10;          // row in [K]
            int n = (off * 4) & 1023;         // col within its W
            __half2* d = (__half2*)(wcat + (size_t)k * N3 + w * D_ + n);
            d[0] = __floats2half2_rn(v.x * sc, v.y * sc);
            d[1] = __floats2half2_rn(v.z * sc, v.w * sc);
        }
    } else {
        int j = i - (XN4 + 4 * WN4);          // 0..767: bias float4s
        if (j < N3 / 4) {
            int col = j * 4;
            int w = col >> 10;
            int n = col & 1023;
            const float* bs = (w == 0) ? bq : (w == 1) ? bk : bv;
            float sc = (w == 0) ? 0.125f : 1.0f;
            float4 v = *(const float4*)(bs + n);
            float4 o = { v.x * sc, v.y * sc, v.z * sc, v.w * sc };
            *(float4*)(bcat + col) = o;
        }
    }
}

// ---------------------------------------------------------------------------
// FP16 GEMM (parametric N): out = A[M,K] @ W[K,N] + bias.
// mode 0: fp32 [M,1024]; mode 1: fp16 QKV scatter (N=3072, col>>10 selects).
// ---------------------------------------------------------------------------
#define GSTR 72
#define BSTR 136
#define ABYT (128 * GSTR * 2)
#define BBYT (64 * BSTR * 2)
#define STAGEB (ABYT + BBYT)
#define GSMB (3 * STAGEB)

extern __shared__ char tsm[];

#define GEMM_ISSUE(t)                                                        \
    do {                                                                     \
        char* sbase = tsm + ((t) % 3) * STAGEB;                              \
        _Pragma("unroll")                                                    \
        for (int ii = 0; ii < 4; ii++) {                                     \
            int idx = ii * 256 + tid;                                        \
            int ra = idx >> 3, sa = idx & 7;                                 \
            cp_async16(sbase + ra * (GSTR * 2) + sa * 16,                    \
                       Ag + (size_t)ra * D_ + (t) * 64 + sa * 8);            \
            int rb = idx >> 4, sg = idx & 15;                                \
            cp_async16(sbase + ABYT + rb * (BSTR * 2) + sg * 16,             \
                       Bg + (size_t)((t) * 64 + rb) * N + sg * 8);           \
        }                                                                    \
        asm volatile("cp.async.commit_group;");                              \
    } while (0)

__global__ void __launch_bounds__(256, 2) gemm_f16_kernel(
    const __half* __restrict__ A, const __half* __restrict__ W,
    const float* __restrict__ bias, int N, int mode,
    void* __restrict__ o0, void* __restrict__ o1, void* __restrict__ o2)
{
    const int tid  = threadIdx.x;
    const int warp = tid >> 5;
    const int lane = tid & 31;
    const int g    = lane >> 2;
    const int tig  = lane & 3;
    const int wm   = (warp >> 2) * 64;
    const int wn   = (warp & 3) * 32;
    const int bm   = blockIdx.y * 128;
    const int bn   = blockIdx.x * 128;

    const __half* Ag = A + (size_t)bm * D_;
    const __half* Bg = W + bn;

    const int a_r = (lane & 7) + ((lane >> 3) & 1) * 8;
    const int a_c = (lane >> 4) * 8;
    const int kb_r = (lane & 7) + ((lane >> 3) & 1) * 8;
    const int kb_n = (lane >> 4) * 8;

    float acc[16][4];
#pragma unroll
    for (int f = 0; f < 16; f++)
#pragma unroll
        for (int e = 0; e < 4; e++) acc[f][e] = 0.0f;

    const uint32_t sb = smem_u32(tsm);
    const int NT = D_ / 64;
    GEMM_ISSUE(0);
    GEMM_ISSUE(1);

    for (int t = 0; t < NT; t++) {
        if (t < NT - 1) asm volatile("cp.async.wait_group 1;");
        else            asm volatile("cp.async.wait_group 0;");
        __syncthreads();

        if (t + 2 < NT) GEMM_ISSUE(t + 2);

        uint32_t abase = sb + (t % 3) * STAGEB
                       + (uint32_t)(((wm + a_r) * GSTR + a_c) * 2);
        uint32_t bbase = sb + (t % 3) * STAGEB + ABYT
                       + (uint32_t)((kb_r * BSTR + wn + kb_n) * 2);

#pragma unroll
        for (int ks = 0; ks < 4; ks++) {
            unsigned af[4][4];
#pragma unroll
            for (int i = 0; i < 4; i++)
                ldsm_x4(af[i][0], af[i][1], af[i][2], af[i][3],
                        abase + ks * 32 + i * 16 * GSTR * 2);
            unsigned bf[4][2];
#pragma unroll
            for (int jp = 0; jp < 2; jp++)
                ldsm_x4_t(bf[2 * jp][0], bf[2 * jp][1],
                          bf[2 * jp + 1][0], bf[2 * jp + 1][1],
                          bbase + ks * 16 * BSTR * 2 + jp * 32);
#pragma unroll
            for (int i = 0; i < 4; i++)
#pragma unroll
                for (int j = 0; j < 4; j++)
                    mma_f16(acc[i * 4 + j], af[i], bf[j][0], bf[j][1]);
        }
    }

    // ---- Epilogue ----
    // mode 1: proj select (uniform per CTA since 128 | 1024)
    __half* qkv_dst = 0;
    if (mode == 1) {
        int proj = bn >> 10;
        qkv_dst = (__half*)((proj == 0) ? o0 : (proj == 1) ? o1 : o2);
    }

#pragma unroll
    for (int i = 0; i < 4; i++) {
#pragma unroll
        for (int j = 0; j < 4; j++) {
            const float* d = acc[i * 4 + j];
            int col = bn + wn + j * 8 + 2 * tig;
            float2 b2 = *(const float2*)(bias + col);
            int row_lo = bm + wm + i * 16 + g;
            int row_hi = row_lo + 8;
            float2 vlo = { d[0] + b2.x, d[1] + b2.y };
            float2 vhi = { d[2] + b2.x, d[3] + b2.y };
            if (mode == 0) {
                float* of = (float*)o0;
                *(float2*)(of + (size_t)row_lo * D_ + col) = vlo;
                *(float2*)(of + (size_t)row_hi * D_ + col) = vhi;
            } else {
                int cn = col & 1023;
                int h = cn / HD_, dd = cn % HD_;
                int b0i = row_lo / S_, s0 = row_lo % S_;
                int b1i = row_hi / S_, s1 = row_hi % S_;
                *(__half2*)(qkv_dst + ((size_t)((b0i * H_ + h) * S_ + s0)) * HD_ + dd)
                    = __floats2half2_rn(vlo.x, vlo.y);
                *(__half2*)(qkv_dst + ((size_t)((b1i * H_ + h) * S_ + s1)) * HD_ + dd)
                    = __floats2half2_rn(vhi.x, vhi.y);
            }
        }
    }
}

// ---------------------------------------------------------------------------
// Flash attention fp16 (R13 version, unchanged).
// ---------------------------------------------------------------------------
#define AKV 64
#define AQ  64
#define KSTR 72

__global__ void __launch_bounds__(128, 4) attn_kernel(
    const __half* __restrict__ Qb, const __half* __restrict__ Kb,
    const __half* __restrict__ Vb, __half* __restrict__ Ob)
{
    __shared__ __half Ks0[64 * KSTR];
    __shared__ __half Ks1[64 * KSTR];
    __shared__ __half Vts[64 * KSTR];

    const int bh   = blockIdx.y;
    const int qt   = blockIdx.x;
    const int tid  = threadIdx.x;
    const int warp = tid >> 5;
    const int lane = tid & 31;
    const int g    = lane >> 2;
    const int tig  = lane & 3;

    const int b_r = (lane & 7) + ((lane >> 4) & 1) * 8;
    const int b_c = ((lane >> 3) & 1) * 8;
    const int kb_r = (lane & 7) + ((lane >> 3) & 1) * 8;
    const int kb_n = (lane >> 4) * 8;

    const __half* Kbase = Kb + (size_t)bh * S_ * HD_;
    const __half* Vbase = Vb + (size_t)bh * S_ * HD_;

    {
#pragma unroll
        for (int i = 0; i < 4; i++) {
            int idx = i * 128 + tid;
            int r = idx >> 3, seg = idx & 7;
            cp_async16((char*)Ks0 + r * (KSTR * 2) + seg * 16,
                       Kbase + (size_t)r * HD_ + seg * 8);
            cp_async16((char*)Vts + r * (KSTR * 2) + seg * 16,
                       Vbase + (size_t)r * HD_ + seg * 8);
        }
        asm volatile("cp.async.commit_group;");
    }

    const int qrow0 = qt * AQ + warp * 16;
    const __half* Qp = Qb + ((size_t)bh * S_ + qrow0) * HD_;
    unsigned qa[4][4];
#pragma unroll
    for (int kc = 0; kc < 4; kc++) {
        int kh = kc * 16;
        qa[kc][0] = *(const unsigned*)(Qp + (size_t)g * HD_ + kh + 2 * tig);
        qa[kc][1] = *(const unsigned*)(Qp + (size_t)(g + 8) * HD_ + kh + 2 * tig);
        qa[kc][2] = *(const unsigned*)(Qp + (size_t)g * HD_ + kh + 8 + 2 * tig);
        qa[kc][3] = *(const unsigned*)(Qp + (size_t)(g + 8) * HD_ + kh + 8 + 2 * tig);
    }

    const uint32_t ks0b = smem_u32(Ks0) + (uint32_t)((b_r * KSTR + b_c) * 2);
    const uint32_t ks1b = smem_u32(Ks1) + (uint32_t)((b_r * KSTR + b_c) * 2);
    const uint32_t vtsb = smem_u32(Vts) + (uint32_t)((kb_r * KSTR + kb_n) * 2);

    float o[8][4];
#pragma unroll
    for (int j = 0; j < 8; j++)
#pragma unroll
        for (int e = 0; e < 4; e++) o[j][e] = 0.0f;
    float m_lo = -1e30f, m_hi = -1e30f;
    float l_lo = 0.0f,   l_hi = 0.0f;
    const unsigned FULL = 0xffffffffu;

    const int NT = S_ / AKV;
    for (int kt = 0; kt < NT; kt++) {
        if (kt + 1 < NT) {
            __half* Kd = ((kt + 1) & 1) ? Ks1 : Ks0;
            const __half* Kp = Kbase + (size_t)(kt + 1) * AKV * HD_;
#pragma unroll
            for (int i = 0; i < 4; i++) {
                int idx = i * 128 + tid;
                int r = idx >> 3, seg = idx & 7;
                cp_async16((char*)Kd + r * (KSTR * 2) + seg * 16,
                           Kp + (size_t)r * HD_ + seg * 8);
            }
            asm volatile("cp.async.commit_group;");
            asm volatile("cp.async.wait_group 1;");
        } else {
            asm volatile("cp.async.wait_group 0;");
        }
        __syncthreads();

        const uint32_t ksb = (kt & 1) ? ks1b : ks0b;

        float s[8][4];
#pragma unroll
        for (int j = 0; j < 8; j++)
#pragma unroll
            for (int e = 0; e < 4; e++) s[j][e] = 0.0f;

#pragma unroll
        for (int kc = 0; kc < 4; kc++) {
            uint32_t ka = ksb + kc * 32;
#pragma unroll
            for (int jp = 0; jp < 4; jp++) {
                unsigned b00, b01, b10, b11;
                ldsm_x4(b00, b01, b10, b11, ka + jp * 16 * KSTR * 2);
                mma_f16(s[2 * jp],     qa[kc], b00, b01);
                mma_f16(s[2 * jp + 1], qa[kc], b10, b11);
            }
        }

        float mx_lo = -1e30f, mx_hi = -1e30f;
#pragma unroll
        for (int j = 0; j < 8; j++) {
            mx_lo = fmaxf(mx_lo, fmaxf(s[j][0], s[j][1]));
            mx_hi = fmaxf(mx_hi, fmaxf(s[j][2], s[j][3]));
        }
        mx_lo = fmaxf(mx_lo, __shfl_xor_sync(FULL, mx_lo, 1));
        mx_lo = fmaxf(mx_lo, __shfl_xor_sync(FULL, mx_lo, 2));
        mx_hi = fmaxf(mx_hi, __shfl_xor_sync(FULL, mx_hi, 1));
        mx_hi = fmaxf(mx_hi, __shfl_xor_sync(FULL, mx_hi, 2));

        float mn_lo = fmaxf(m_lo, mx_lo);
        float mn_hi = fmaxf(m_hi, mx_hi);
        float al_lo = __expf(m_lo - mn_lo);
        float al_hi = __expf(m_hi - mn_hi);
        m_lo = mn_lo; m_hi = mn_hi;

        float sum_lo = 0.0f, sum_hi = 0.0f;
#pragma unroll
        for (int j = 0; j < 8; j++) {
            float p0 = __expf(s[j][0] - mn_lo);
            float p1 = __expf(s[j][1] - mn_lo);
            float p2 = __expf(s[j][2] - mn_hi);
            float p3 = __expf(s[j][3] - mn_hi);
            sum_lo += p0 + p1;
            sum_hi += p2 + p3;
            s[j][0] = p0; s[j][1] = p1; s[j][2] = p2; s[j][3] = p3;
        }
        sum_lo += __shfl_xor_sync(FULL, sum_lo, 1);
        sum_lo += __shfl_xor_sync(FULL, sum_lo, 2);
        sum_hi += __shfl_xor_sync(FULL, sum_hi, 1);
        sum_hi += __shfl_xor_sync(FULL, sum_hi, 2);
        l_lo = l_lo * al_lo + sum_lo;
        l_hi = l_hi * al_hi + sum_hi;

#pragma unroll
        for (int j = 0; j < 8; j++) {
            o[j][0] *= al_lo; o[j][1] *= al_lo;
            o[j][2] *= al_hi; o[j][3] *= al_hi;
        }

#pragma unroll
        for (int kc = 0; kc < 4; kc++) {
            unsigned pa[4];
            pa[0] = pack_h2(s[2 * kc][0],     s[2 * kc][1]);
            pa[1] = pack_h2(s[2 * kc][2],     s[2 * kc][3]);
            pa[2] = pack_h2(s[2 * kc + 1][0], s[2 * kc + 1][1]);
            pa[3] = pack_h2(s[2 * kc + 1][2], s[2 * kc + 1][3]);
            uint32_t ka = vtsb + kc * 16 * KSTR * 2;
#pragma unroll
            for (int jp = 0; jp < 4; jp++) {
                unsigned b00, b01, b10, b11;
                ldsm_x4_t(b00, b01, b10, b11, ka + jp * 32);
                mma_f16(o[2 * jp],     pa, b00, b01);
                mma_f16(o[2 * jp + 1], pa, b10, b11);
            }
        }
        __syncthreads();

        if (kt + 1 < NT) {
            const __half* Vp = Vbase + (size_t)(kt + 1) * AKV * HD_;
#pragma unroll
            for (int i = 0; i < 4; i++) {
                int idx = i * 128 + tid;
                int r = idx >> 3, seg = idx & 7;
                cp_async16((char*)Vts + r * (KSTR * 2) + seg * 16,
                           Vp + (size_t)r * HD_ + seg * 8);
            }
            asm volatile("cp.async.commit_group;");
        }
    }

    float inv_lo = 1.0f / l_lo;
    float inv_hi = 1.0f / l_hi;
    int b = bh / H_, h = bh % H_;
    __half* orow_lo = Ob + ((size_t)(b * S_ + qrow0 + g)) * D_ + h * HD_;
    __half* orow_hi = Ob + ((size_t)(b * S_ + qrow0 + g + 8)) * D_ + h * HD_;
#pragma unroll
    for (int jn = 0; jn < 8; jn++) {
        *(__half2*)(orow_lo + jn * 8 + 2 * tig)
            = __floats2half2_rn(o[jn][0] * inv_lo, o[jn][1] * inv_lo);
        *(__half2*)(orow_hi + jn * 8 + 2 * tig)
            = __floats2half2_rn(o[jn][2] * inv_hi, o[jn][3] * inv_hi);
    }
}

// ---------------------------------------------------------------------------
// Launch
// ---------------------------------------------------------------------------
extern "C" void kernel_launch(void* const* d_in, const int* in_sizes, int n_in,
                              void* d_out, int out_size)
{
    (void)in_sizes; (void)n_in; (void)out_size;
    const float* x  = (const float*)d_in[0];
    const float* Wq = (const float*)d_in[1];
    const float* bq = (const float*)d_in[2];
    const float* Wk = (const float*)d_in[3];
    const float* bk = (const float*)d_in[4];
    const float* Wv = (const float*)d_in[5];
    const float* bv = (const float*)d_in[6];
    const float* Wo = (const float*)d_in[7];
    const float* bo = (const float*)d_in[8];
    float* out = (float*)d_out;

    void *pq, *pk, *pv, *patt, *pxt, *pwc, *pwo, *pbc;
    cudaGetSymbolAddress(&pq, g_q);
    cudaGetSymbolAddress(&pk, g_k);
    cudaGetSymbolAddress(&pv, g_v);
    cudaGetSymbolAddress(&patt, g_att);
    cudaGetSymbolAddress(&pxt, g_xt);
    cudaGetSymbolAddress(&pwc, g_wcat);
    cudaGetSymbolAddress(&pwo, g_wo);
    cudaGetSymbolAddress(&pbc, g_bcat);
    __half* qb = (__half*)pq;
    __half* kb = (__half*)pk;
    __half* vb = (__half*)pv;
    __half* ab = (__half*)patt;
    __half* xt = (__half*)pxt;
    __half* wc = (__half*)pwc;
    __half* wo = (__half*)pwo;
    float*  bc = (float*)pbc;

    cudaFuncSetAttribute(gemm_f16_kernel,
                         cudaFuncAttributeMaxDynamicSharedMemorySize, GSMB);

    // 1) Prep (x, wcat with folded 0.125, wo, bcat)
    int nthr = XN4 + 4 * WN4 + N3 / 4;
    cvt_all_kernel<<<(nthr + 255) / 256, 256>>>(x, Wq, Wk, Wv, Wo, bq, bk, bv,
                                                xt, wc, wo, bc);

    // 2) Fused QKV projection: one GEMM, N=3072
    dim3 qgrid(N3 / 128, M_TOT / 128);            // (24, 32) = 768 CTAs
    gemm_f16_kernel<<<qgrid, 256, GSMB>>>(xt, wc, bc, N3, 1, qb, kb, vb);

    // 3) Attention
    dim3 agrid(S_ / AQ, B_ * H_);                 // (32, 32)
    attn_kernel<<<agrid, 128>>>(qb, kb, vb, ab);

    // 4) Output projection
    dim3 ogrid(D_ / 128, M_TOT / 128);            // (8, 32)
    gemm_f16_kernel<<<ogrid, 256, GSMB>>>(ab, wo, bo, D_, 0, out, 0, 0);
}

// round 15
// speedup vs baseline: 1.0693x; 1.0693x over previous
#include <cuda_runtime.h>
#include <cuda_fp16.h>
#include <cstdint>

// Problem constants (fixed shapes)
#define B_   2
#define S_   2048
#define D_   1024
#define H_   16
#define HD_  64
#define M_TOT (B_ * S_)   // 4096

// ---------------------------------------------------------------------------
// Scratch buffers (fp16; Q pre-scaled by 1/sqrt(HD); all natural layouts)
// ---------------------------------------------------------------------------
__device__ __half g_q[B_ * H_ * S_ * HD_];    // [B,H,S,HD]
__device__ __half g_k[B_ * H_ * S_ * HD_];    // [B,H,S,HD]
__device__ __half g_v[B_ * H_ * S_ * HD_];    // [B,H,S,HD]
__device__ __half g_att[B_ * S_ * D_];        // [B,S,D]
__device__ __half g_xt[M_TOT * D_];           // x fp16 [M,K]
__device__ __half g_wt[4 * D_ * D_];          // W fp16 [K,N] x4 (natural)

// ---------------------------------------------------------------------------
// Helpers
// ---------------------------------------------------------------------------
__device__ __forceinline__ void mma_f16(float* d, const unsigned* a,
                                        unsigned b0, unsigned b1) {
    asm volatile(
        "mma.sync.aligned.m16n8k16.row.col.f32.f16.f16.f32 "
        "{%0,%1,%2,%3}, {%4,%5,%6,%7}, {%8,%9}, {%0,%1,%2,%3};"
        : "+f"(d[0]), "+f"(d[1]), "+f"(d[2]), "+f"(d[3])
        : "r"(a[0]), "r"(a[1]), "r"(a[2]), "r"(a[3]), "r"(b0), "r"(b1));
}

__device__ __forceinline__ void cp_async16(void* smem_dst, const void* gmem_src) {
    unsigned saddr = (unsigned)__cvta_generic_to_shared(smem_dst);
    asm volatile("cp.async.cg.shared.global [%0], [%1], 16;"
                 :: "r"(saddr), "l"(gmem_src));
}

__device__ __forceinline__ unsigned pack_h2(float lo, float hi) {
    __half2 h = __floats2half2_rn(lo, hi);
    return *reinterpret_cast<unsigned*>(&h);
}

__device__ __forceinline__ void ldsm_x4(unsigned& d0, unsigned& d1,
                                        unsigned& d2, unsigned& d3,
                                        uint32_t addr) {
    asm volatile("ldmatrix.sync.aligned.m8n8.x4.shared.b16 {%0,%1,%2,%3}, [%4];"
                 : "=r"(d0), "=r"(d1), "=r"(d2), "=r"(d3) : "r"(addr));
}

__device__ __forceinline__ void ldsm_x4_t(unsigned& d0, unsigned& d1,
                                          unsigned& d2, unsigned& d3,
                                          uint32_t addr) {
    asm volatile("ldmatrix.sync.aligned.m8n8.x4.trans.shared.b16 {%0,%1,%2,%3}, [%4];"
                 : "=r"(d0), "=r"(d1), "=r"(d2), "=r"(d3) : "r"(addr));
}

__device__ __forceinline__ uint32_t smem_u32(const void* p) {
    return (uint32_t)__cvta_generic_to_shared(p);
}

// ---------------------------------------------------------------------------
// Prep: x AND all W -> fp16 (pure elementwise, one kernel)
// ---------------------------------------------------------------------------
#define XN4 (M_TOT * D_ / 4)       // 1048576
#define WN4 (D_ * D_ / 4)          // 262144 each

__global__ void __launch_bounds__(256) cvt_all_kernel(
    const float* __restrict__ x,
    const float* __restrict__ wq, const float* __restrict__ wk,
    const float* __restrict__ wv, const float* __restrict__ wo,
    __half* __restrict__ xt, __half* __restrict__ wt)
{
    int i = blockIdx.x * 256 + threadIdx.x;
    const float4* s;
    __half2* d;
    if (i < XN4) {
        s = (const float4*)x + i;
        d = (__half2*)xt + 2 * i;
    } else {
        int j = i - XN4;
        int w = j >> 18;
        int off = j & (WN4 - 1);
        const float* ws = (w == 0) ? wq : (w == 1) ? wk : (w == 2) ? wv : wo;
        s = (const float4*)ws + off;
        d = (__half2*)(wt + (size_t)w * D_ * D_) + 2 * off;
    }
    float4 v = *s;
    d[0] = __floats2half2_rn(v.x, v.y);
    d[1] = __floats2half2_rn(v.z, v.w);
}

// ---------------------------------------------------------------------------
// FP16 GEMM (R13 exact): out = A[M,K] @ W[K,N] + bias, compile-time N=D_.
// mode 0: fp32 [M,N]; mode 1: fp16 scatter [B,H,S,HD].
// ---------------------------------------------------------------------------
#define GSTR 72
#define BSTR 136
#define ABYT (128 * GSTR * 2)
#define BBYT (64 * BSTR * 2)
#define STAGEB (ABYT + BBYT)
#define GSMB (3 * STAGEB)

extern __shared__ char tsm[];

#define GEMM_ISSUE(t)                                                        \
    do {                                                                     \
        char* sbase = tsm + ((t) % 3) * STAGEB;                              \
        _Pragma("unroll")                                                    \
        for (int ii = 0; ii < 4; ii++) {                                     \
            int idx = ii * 256 + tid;                                        \
            int ra = idx >> 3, sa = idx & 7;                                 \
            cp_async16(sbase + ra * (GSTR * 2) + sa * 16,                    \
                       Ag + (size_t)ra * D_ + (t) * 64 + sa * 8);            \
            int rb = idx >> 4, sg = idx & 15;                                \
            cp_async16(sbase + ABYT + rb * (BSTR * 2) + sg * 16,             \
                       Bg + (size_t)((t) * 64 + rb) * D_ + sg * 8);          \
        }                                                                    \
        asm volatile("cp.async.commit_group;");                              \
    } while (0)

__global__ void __launch_bounds__(256, 2) gemm_f16_kernel(
    const __half* __restrict__ A, const __half* __restrict__ W,
    const float* __restrict__ bias, void* __restrict__ out,
    int mode, float oscale)
{
    const int tid  = threadIdx.x;
    const int warp = tid >> 5;
    const int lane = tid & 31;
    const int g    = lane >> 2;
    const int tig  = lane & 3;
    const int wm   = (warp >> 2) * 64;
    const int wn   = (warp & 3) * 32;
    const int bm   = blockIdx.y * 128;
    const int bn   = blockIdx.x * 128;

    const __half* Ag = A + (size_t)bm * D_;
    const __half* Bg = W + bn;

    const int a_r = (lane & 7) + ((lane >> 3) & 1) * 8;
    const int a_c = (lane >> 4) * 8;
    const int kb_r = (lane & 7) + ((lane >> 3) & 1) * 8;
    const int kb_n = (lane >> 4) * 8;

    float acc[16][4];
#pragma unroll
    for (int f = 0; f < 16; f++)
#pragma unroll
        for (int e = 0; e < 4; e++) acc[f][e] = 0.0f;

    const uint32_t sb = smem_u32(tsm);
    const int NT = D_ / 64;
    GEMM_ISSUE(0);
    GEMM_ISSUE(1);

    for (int t = 0; t < NT; t++) {
        if (t < NT - 1) asm volatile("cp.async.wait_group 1;");
        else            asm volatile("cp.async.wait_group 0;");
        __syncthreads();

        if (t + 2 < NT) GEMM_ISSUE(t + 2);

        uint32_t abase = sb + (t % 3) * STAGEB
                       + (uint32_t)(((wm + a_r) * GSTR + a_c) * 2);
        uint32_t bbase = sb + (t % 3) * STAGEB + ABYT
                       + (uint32_t)((kb_r * BSTR + wn + kb_n) * 2);

#pragma unroll
        for (int ks = 0; ks < 4; ks++) {
            unsigned af[4][4];
#pragma unroll
            for (int i = 0; i < 4; i++)
                ldsm_x4(af[i][0], af[i][1], af[i][2], af[i][3],
                        abase + ks * 32 + i * 16 * GSTR * 2);
            unsigned bf[4][2];
#pragma unroll
            for (int jp = 0; jp < 2; jp++)
                ldsm_x4_t(bf[2 * jp][0], bf[2 * jp][1],
                          bf[2 * jp + 1][0], bf[2 * jp + 1][1],
                          bbase + ks * 16 * BSTR * 2 + jp * 32);
#pragma unroll
            for (int i = 0; i < 4; i++)
#pragma unroll
                for (int j = 0; j < 4; j++)
                    mma_f16(acc[i * 4 + j], af[i], bf[j][0], bf[j][1]);
        }
    }

    // ---- Epilogue ----
#pragma unroll
    for (int i = 0; i < 4; i++) {
#pragma unroll
        for (int j = 0; j < 4; j++) {
            const float* d = acc[i * 4 + j];
            int col = bn + wn + j * 8 + 2 * tig;
            float2 b2 = *(const float2*)(bias + col);
            int row_lo = bm + wm + i * 16 + g;
            int row_hi = row_lo + 8;
            float2 vlo = { (d[0] + b2.x) * oscale, (d[1] + b2.y) * oscale };
            float2 vhi = { (d[2] + b2.x) * oscale, (d[3] + b2.y) * oscale };
            if (mode == 0) {
                float* of = (float*)out;
                *(float2*)(of + (size_t)row_lo * D_ + col) = vlo;
                *(float2*)(of + (size_t)row_hi * D_ + col) = vhi;
            } else {
                __half* oh = (__half*)out;
                int h = col / HD_, dd = col % HD_;
                int b0i = row_lo / S_, s0 = row_lo % S_;
                int b1i = row_hi / S_, s1 = row_hi % S_;
                *(__half2*)(oh + ((size_t)((b0i * H_ + h) * S_ + s0)) * HD_ + dd)
                    = __floats2half2_rn(vlo.x, vlo.y);
                *(__half2*)(oh + ((size_t)((b1i * H_ + h) * S_ + s1)) * HD_ + dd)
                    = __floats2half2_rn(vhi.x, vhi.y);
            }
        }
    }
}

// ---------------------------------------------------------------------------
// Flash attention fp16 v2: K AND V double-buffered, ONE sync per KV tile.
// Loop: wait(all) -> sync -> issue next K+V (one group) -> compute.
// ---------------------------------------------------------------------------
#define AKV 64
#define AQ  64
#define KSTR 72

__global__ void __launch_bounds__(128, 4) attn_kernel(
    const __half* __restrict__ Qb, const __half* __restrict__ Kb,
    const __half* __restrict__ Vb, __half* __restrict__ Ob)
{
    __shared__ __half Ks0[64 * KSTR];
    __shared__ __half Ks1[64 * KSTR];
    __shared__ __half Vs0[64 * KSTR];
    __shared__ __half Vs1[64 * KSTR];

    const int bh   = blockIdx.y;
    const int qt   = blockIdx.x;
    const int tid  = threadIdx.x;
    const int warp = tid >> 5;
    const int lane = tid & 31;
    const int g    = lane >> 2;
    const int tig  = lane & 3;

    const int b_r = (lane & 7) + ((lane >> 4) & 1) * 8;
    const int b_c = ((lane >> 3) & 1) * 8;
    const int kb_r = (lane & 7) + ((lane >> 3) & 1) * 8;
    const int kb_n = (lane >> 4) * 8;

    const __half* Kbase = Kb + (size_t)bh * S_ * HD_;
    const __half* Vbase = Vb + (size_t)bh * S_ * HD_;

    // Prologue: tile 0 K+V (one group) into buffer 0
    {
#pragma unroll
        for (int i = 0; i < 4; i++) {
            int idx = i * 128 + tid;
            int r = idx >> 3, seg = idx & 7;
            cp_async16((char*)Ks0 + r * (KSTR * 2) + seg * 16,
                       Kbase + (size_t)r * HD_ + seg * 8);
            cp_async16((char*)Vs0 + r * (KSTR * 2) + seg * 16,
                       Vbase + (size_t)r * HD_ + seg * 8);
        }
        asm volatile("cp.async.commit_group;");
    }

    const int qrow0 = qt * AQ + warp * 16;
    const __half* Qp = Qb + ((size_t)bh * S_ + qrow0) * HD_;
    unsigned qa[4][4];
#pragma unroll
    for (int kc = 0; kc < 4; kc++) {
        int kh = kc * 16;
        qa[kc][0] = *(const unsigned*)(Qp + (size_t)g * HD_ + kh + 2 * tig);
        qa[kc][1] = *(const unsigned*)(Qp + (size_t)(g + 8) * HD_ + kh + 2 * tig);
        qa[kc][2] = *(const unsigned*)(Qp + (size_t)g * HD_ + kh + 8 + 2 * tig);
        qa[kc][3] = *(const unsigned*)(Qp + (size_t)(g + 8) * HD_ + kh + 8 + 2 * tig);
    }

    const uint32_t ks0b = smem_u32(Ks0) + (uint32_t)((b_r * KSTR + b_c) * 2);
    const uint32_t ks1b = smem_u32(Ks1) + (uint32_t)((b_r * KSTR + b_c) * 2);
    const uint32_t vs0b = smem_u32(Vs0) + (uint32_t)((kb_r * KSTR + kb_n) * 2);
    const uint32_t vs1b = smem_u32(Vs1) + (uint32_t)((kb_r * KSTR + kb_n) * 2);

    float o[8][4];
#pragma unroll
    for (int j = 0; j < 8; j++)
#pragma unroll
        for (int e = 0; e < 4; e++) o[j][e] = 0.0f;
    float m_lo = -1e30f, m_hi = -1e30f;
    float l_lo = 0.0f,   l_hi = 0.0f;
    const unsigned FULL = 0xffffffffu;

    const int NT = S_ / AKV;
    for (int kt = 0; kt < NT; kt++) {
        // Drain tile kt's loads; sync guards buffer (kt+1)&1 reuse.
        asm volatile("cp.async.wait_group 0;");
        __syncthreads();

        // Issue tile kt+1 (K+V, one group) into the other buffers.
        if (kt + 1 < NT) {
            __half* Kd = ((kt + 1) & 1) ? Ks1 : Ks0;
            __half* Vd = ((kt + 1) & 1) ? Vs1 : Vs0;
            const __half* Kp = Kbase + (size_t)(kt + 1) * AKV * HD_;
            const __half* Vp = Vbase + (size_t)(kt + 1) * AKV * HD_;
#pragma unroll
            for (int i = 0; i < 4; i++) {
                int idx = i * 128 + tid;
                int r = idx >> 3, seg = idx & 7;
                cp_async16((char*)Kd + r * (KSTR * 2) + seg * 16,
                           Kp + (size_t)r * HD_ + seg * 8);
                cp_async16((char*)Vd + r * (KSTR * 2) + seg * 16,
                           Vp + (size_t)r * HD_ + seg * 8);
            }
            asm volatile("cp.async.commit_group;");
        }

        const uint32_t ksb = (kt & 1) ? ks1b : ks0b;
        const uint32_t vsb = (kt & 1) ? vs1b : vs0b;

        // ---- S = Q @ K^T ----
        float s[8][4];
#pragma unroll
        for (int j = 0; j < 8; j++)
#pragma unroll
            for (int e = 0; e < 4; e++) s[j][e] = 0.0f;

#pragma unroll
        for (int kc = 0; kc < 4; kc++) {
            uint32_t ka = ksb + kc * 32;
#pragma unroll
            for (int jp = 0; jp < 4; jp++) {
                unsigned b00, b01, b10, b11;
                ldsm_x4(b00, b01, b10, b11, ka + jp * 16 * KSTR * 2);
                mma_f16(s[2 * jp],     qa[kc], b00, b01);
                mma_f16(s[2 * jp + 1], qa[kc], b10, b11);
            }
        }

        // ---- Online softmax ----
        float mx_lo = -1e30f, mx_hi = -1e30f;
#pragma unroll
        for (int j = 0; j < 8; j++) {
            mx_lo = fmaxf(mx_lo, fmaxf(s[j][0], s[j][1]));
            mx_hi = fmaxf(mx_hi, fmaxf(s[j][2], s[j][3]));
        }
        mx_lo = fmaxf(mx_lo, __shfl_xor_sync(FULL, mx_lo, 1));
        mx_lo = fmaxf(mx_lo, __shfl_xor_sync(FULL, mx_lo, 2));
        mx_hi = fmaxf(mx_hi, __shfl_xor_sync(FULL, mx_hi, 1));
        mx_hi = fmaxf(mx_hi, __shfl_xor_sync(FULL, mx_hi, 2));

        float mn_lo = fmaxf(m_lo, mx_lo);
        float mn_hi = fmaxf(m_hi, mx_hi);
        float al_lo = __expf(m_lo - mn_lo);
        float al_hi = __expf(m_hi - mn_hi);
        m_lo = mn_lo; m_hi = mn_hi;

        float sum_lo = 0.0f, sum_hi = 0.0f;
#pragma unroll
        for (int j = 0; j < 8; j++) {
            float p0 = __expf(s[j][0] - mn_lo);
            float p1 = __expf(s[j][1] - mn_lo);
            float p2 = __expf(s[j][2] - mn_hi);
            float p3 = __expf(s[j][3] - mn_hi);
            sum_lo += p0 + p1;
            sum_hi += p2 + p3;
            s[j][0] = p0; s[j][1] = p1; s[j][2] = p2; s[j][3] = p3;
        }
        sum_lo += __shfl_xor_sync(FULL, sum_lo, 1);
        sum_lo += __shfl_xor_sync(FULL, sum_lo, 2);
        sum_hi += __shfl_xor_sync(FULL, sum_hi, 1);
        sum_hi += __shfl_xor_sync(FULL, sum_hi, 2);
        l_lo = l_lo * al_lo + sum_lo;
        l_hi = l_hi * al_hi + sum_hi;

#pragma unroll
        for (int j = 0; j < 8; j++) {
            o[j][0] *= al_lo; o[j][1] *= al_lo;
            o[j][2] *= al_hi; o[j][3] *= al_hi;
        }

        // ---- O += P @ V ----
#pragma unroll
        for (int kc = 0; kc < 4; kc++) {
            unsigned pa[4];
            pa[0] = pack_h2(s[2 * kc][0],     s[2 * kc][1]);
            pa[1] = pack_h2(s[2 * kc][2],     s[2 * kc][3]);
            pa[2] = pack_h2(s[2 * kc + 1][0], s[2 * kc + 1][1]);
            pa[3] = pack_h2(s[2 * kc + 1][2], s[2 * kc + 1][3]);
            uint32_t ka = vsb + kc * 16 * KSTR * 2;
#pragma unroll
            for (int jp = 0; jp < 4; jp++) {
                unsigned b00, b01, b10, b11;
                ldsm_x4_t(b00, b01, b10, b11, ka + jp * 32);
                mma_f16(o[2 * jp],     pa, b00, b01);
                mma_f16(o[2 * jp + 1], pa, b10, b11);
            }
        }
        // no trailing sync: next iteration's top sync covers buffer reuse
    }

    // ---- Normalize + write fp16 to [B,S,D] ----
    float inv_lo = 1.0f / l_lo;
    float inv_hi = 1.0f / l_hi;
    int b = bh / H_, h = bh % H_;
    __half* orow_lo = Ob + ((size_t)(b * S_ + qrow0 + g)) * D_ + h * HD_;
    __half* orow_hi = Ob + ((size_t)(b * S_ + qrow0 + g + 8)) * D_ + h * HD_;
#pragma unroll
    for (int jn = 0; jn < 8; jn++) {
        *(__half2*)(orow_lo + jn * 8 + 2 * tig)
            = __floats2half2_rn(o[jn][0] * inv_lo, o[jn][1] * inv_lo);
        *(__half2*)(orow_hi + jn * 8 + 2 * tig)
            = __floats2half2_rn(o[jn][2] * inv_hi, o[jn][3] * inv_hi);
    }
}

// ---------------------------------------------------------------------------
// Launch
// ---------------------------------------------------------------------------
extern "C" void kernel_launch(void* const* d_in, const int* in_sizes, int n_in,
                              void* d_out, int out_size)
{
    (void)in_sizes; (void)n_in; (void)out_size;
    const float* x  = (const float*)d_in[0];
    const float* Wq = (const float*)d_in[1];
    const float* bq = (const float*)d_in[2];
    const float* Wk = (const float*)d_in[3];
    const float* bk = (const float*)d_in[4];
    const float* Wv = (const float*)d_in[5];
    const float* bv = (const float*)d_in[6];
    const float* Wo = (const float*)d_in[7];
    const float* bo = (const float*)d_in[8];
    float* out = (float*)d_out;

    void *pq, *pk, *pv, *patt, *pxt, *pwt;
    cudaGetSymbolAddress(&pq, g_q);
    cudaGetSymbolAddress(&pk, g_k);
    cudaGetSymbolAddress(&pv, g_v);
    cudaGetSymbolAddress(&patt, g_att);
    cudaGetSymbolAddress(&pxt, g_xt);
    cudaGetSymbolAddress(&pwt, g_wt);
    __half* qb = (__half*)pq;
    __half* kb = (__half*)pk;
    __half* vb = (__half*)pv;
    __half* ab = (__half*)patt;
    __half* xt = (__half*)pxt;
    __half* wt = (__half*)pwt;

    cudaFuncSetAttribute(gemm_f16_kernel,
                         cudaFuncAttributeMaxDynamicSharedMemorySize, GSMB);

    // 1) Prep
    int nthr = XN4 + 4 * WN4;
    cvt_all_kernel<<<nthr / 256, 256>>>(x, Wq, Wk, Wv, Wo, xt, wt);

    // 2) QKV projections
    dim3 ggrid(D_ / 128, M_TOT / 128);            // (8, 32)
    gemm_f16_kernel<<<ggrid, 256, GSMB>>>(xt, wt + 0 * (size_t)D_ * D_, bq, qb, 1, 0.125f);
    gemm_f16_kernel<<<ggrid, 256, GSMB>>>(xt, wt + 1 * (size_t)D_ * D_, bk, kb, 1, 1.0f);
    gemm_f16_kernel<<<ggrid, 256, GSMB>>>(xt, wt + 2 * (size_t)D_ * D_, bv, vb, 1, 1.0f);

    // 3) Attention
    dim3 agrid(S_ / AQ, B_ * H_);                 // (32, 32)
    attn_kernel<<<agrid, 128>>>(qb, kb, vb, ab);

    // 4) Output projection
    gemm_f16_kernel<<<ggrid, 256, GSMB>>>(ab, wt + 3 * (size_t)D_ * D_, bo, out, 0, 1.0f);
}

// round 16
// speedup vs baseline: 1.0955x; 1.0245x over previous
#include <cuda_runtime.h>
#include <cuda_fp16.h>
#include <cstdint>

// Problem constants (fixed shapes)
#define B_   2
#define S_   2048
#define D_   1024
#define H_   16
#define HD_  64
#define M_TOT (B_ * S_)   // 4096

// ---------------------------------------------------------------------------
// Scratch buffers (fp16; Q pre-scaled by log2e/sqrt(HD); natural layouts)
// ---------------------------------------------------------------------------
__device__ __half g_q[B_ * H_ * S_ * HD_];    // [B,H,S,HD]
__device__ __half g_k[B_ * H_ * S_ * HD_];    // [B,H,S,HD]
__device__ __half g_v[B_ * H_ * S_ * HD_];    // [B,H,S,HD]
__device__ __half g_att[B_ * S_ * D_];        // [B,S,D]
__device__ __half g_xt[M_TOT * D_];           // x fp16 [M,K]
__device__ __half g_wt[4 * D_ * D_];          // W fp16 [K,N] x4 (natural)

// ---------------------------------------------------------------------------
// Helpers
// ---------------------------------------------------------------------------
__device__ __forceinline__ void mma_f16(float* d, const unsigned* a,
                                        unsigned b0, unsigned b1) {
    asm volatile(
        "mma.sync.aligned.m16n8k16.row.col.f32.f16.f16.f32 "
        "{%0,%1,%2,%3}, {%4,%5,%6,%7}, {%8,%9}, {%0,%1,%2,%3};"
        : "+f"(d[0]), "+f"(d[1]), "+f"(d[2]), "+f"(d[3])
        : "r"(a[0]), "r"(a[1]), "r"(a[2]), "r"(a[3]), "r"(b0), "r"(b1));
}

__device__ __forceinline__ void cp_async16(void* smem_dst, const void* gmem_src) {
    unsigned saddr = (unsigned)__cvta_generic_to_shared(smem_dst);
    asm volatile("cp.async.cg.shared.global [%0], [%1], 16;"
                 :: "r"(saddr), "l"(gmem_src));
}

__device__ __forceinline__ unsigned pack_h2(float lo, float hi) {
    __half2 h = __floats2half2_rn(lo, hi);
    return *reinterpret_cast<unsigned*>(&h);
}

__device__ __forceinline__ float ex2f(float x) {
    float y;
    asm("ex2.approx.f32 %0, %1;" : "=f"(y) : "f"(x));
    return y;
}

__device__ __forceinline__ void ldsm_x4(unsigned& d0, unsigned& d1,
                                        unsigned& d2, unsigned& d3,
                                        uint32_t addr) {
    asm volatile("ldmatrix.sync.aligned.m8n8.x4.shared.b16 {%0,%1,%2,%3}, [%4];"
                 : "=r"(d0), "=r"(d1), "=r"(d2), "=r"(d3) : "r"(addr));
}

__device__ __forceinline__ void ldsm_x4_t(unsigned& d0, unsigned& d1,
                                          unsigned& d2, unsigned& d3,
                                          uint32_t addr) {
    asm volatile("ldmatrix.sync.aligned.m8n8.x4.trans.shared.b16 {%0,%1,%2,%3}, [%4];"
                 : "=r"(d0), "=r"(d1), "=r"(d2), "=r"(d3) : "r"(addr));
}

__device__ __forceinline__ uint32_t smem_u32(const void* p) {
    return (uint32_t)__cvta_generic_to_shared(p);
}

// ---------------------------------------------------------------------------
// Prep: x AND all W -> fp16 (pure elementwise, one kernel)
// ---------------------------------------------------------------------------
#define XN4 (M_TOT * D_ / 4)       // 1048576
#define WN4 (D_ * D_ / 4)          // 262144 each

__global__ void __launch_bounds__(256) cvt_all_kernel(
    const float* __restrict__ x,
    const float* __restrict__ wq, const float* __restrict__ wk,
    const float* __restrict__ wv, const float* __restrict__ wo,
    __half* __restrict__ xt, __half* __restrict__ wt)
{
    int i = blockIdx.x * 256 + threadIdx.x;
    const float4* s;
    __half2* d;
    if (i < XN4) {
        s = (const float4*)x + i;
        d = (__half2*)xt + 2 * i;
    } else {
        int j = i - XN4;
        int w = j >> 18;
        int off = j & (WN4 - 1);
        const float* ws = (w == 0) ? wq : (w == 1) ? wk : (w == 2) ? wv : wo;
        s = (const float4*)ws + off;
        d = (__half2*)(wt + (size_t)w * D_ * D_) + 2 * off;
    }
    float4 v = *s;
    d[0] = __floats2half2_rn(v.x, v.y);
    d[1] = __floats2half2_rn(v.z, v.w);
}

// ---------------------------------------------------------------------------
// FP16 GEMM (frozen R13/R15): out = A[M,K] @ W[K,N] + bias, N=D_ compile-time.
// mode 0: fp32 [M,N]; mode 1: fp16 scatter [B,H,S,HD].
// ---------------------------------------------------------------------------
#define GSTR 72
#define BSTR 136
#define ABYT (128 * GSTR * 2)
#define BBYT (64 * BSTR * 2)
#define STAGEB (ABYT + BBYT)
#define GSMB (3 * STAGEB)

extern __shared__ char tsm[];

#define GEMM_ISSUE(t)                                                        \
    do {                                                                     \
        char* sbase = tsm + ((t) % 3) * STAGEB;                              \
        _Pragma("unroll")                                                    \
        for (int ii = 0; ii < 4; ii++) {                                     \
            int idx = ii * 256 + tid;                                        \
            int ra = idx >> 3, sa = idx & 7;                                 \
            cp_async16(sbase + ra * (GSTR * 2) + sa * 16,                    \
                       Ag + (size_t)ra * D_ + (t) * 64 + sa * 8);            \
            int rb = idx >> 4, sg = idx & 15;                                \
            cp_async16(sbase + ABYT + rb * (BSTR * 2) + sg * 16,             \
                       Bg + (size_t)((t) * 64 + rb) * D_ + sg * 8);          \
        }                                                                    \
        asm volatile("cp.async.commit_group;");                              \
    } while (0)

__global__ void __launch_bounds__(256, 2) gemm_f16_kernel(
    const __half* __restrict__ A, const __half* __restrict__ W,
    const float* __restrict__ bias, void* __restrict__ out,
    int mode, float oscale)
{
    const int tid  = threadIdx.x;
    const int warp = tid >> 5;
    const int lane = tid & 31;
    const int g    = lane >> 2;
    const int tig  = lane & 3;
    const int wm   = (warp >> 2) * 64;
    const int wn   = (warp & 3) * 32;
    const int bm   = blockIdx.y * 128;
    const int bn   = blockIdx.x * 128;

    const __half* Ag = A + (size_t)bm * D_;
    const __half* Bg = W + bn;

    const int a_r = (lane & 7) + ((lane >> 3) & 1) * 8;
    const int a_c = (lane >> 4) * 8;
    const int kb_r = (lane & 7) + ((lane >> 3) & 1) * 8;
    const int kb_n = (lane >> 4) * 8;

    float acc[16][4];
#pragma unroll
    for (int f = 0; f < 16; f++)
#pragma unroll
        for (int e = 0; e < 4; e++) acc[f][e] = 0.0f;

    const uint32_t sb = smem_u32(tsm);
    const int NT = D_ / 64;
    GEMM_ISSUE(0);
    GEMM_ISSUE(1);

    for (int t = 0; t < NT; t++) {
        if (t < NT - 1) asm volatile("cp.async.wait_group 1;");
        else            asm volatile("cp.async.wait_group 0;");
        __syncthreads();

        if (t + 2 < NT) GEMM_ISSUE(t + 2);

        uint32_t abase = sb + (t % 3) * STAGEB
                       + (uint32_t)(((wm + a_r) * GSTR + a_c) * 2);
        uint32_t bbase = sb + (t % 3) * STAGEB + ABYT
                       + (uint32_t)((kb_r * BSTR + wn + kb_n) * 2);

#pragma unroll
        for (int ks = 0; ks < 4; ks++) {
            unsigned af[4][4];
#pragma unroll
            for (int i = 0; i < 4; i++)
                ldsm_x4(af[i][0], af[i][1], af[i][2], af[i][3],
                        abase + ks * 32 + i * 16 * GSTR * 2);
            unsigned bf[4][2];
#pragma unroll
            for (int jp = 0; jp < 2; jp++)
                ldsm_x4_t(bf[2 * jp][0], bf[2 * jp][1],
                          bf[2 * jp + 1][0], bf[2 * jp + 1][1],
                          bbase + ks * 16 * BSTR * 2 + jp * 32);
#pragma unroll
            for (int i = 0; i < 4; i++)
#pragma unroll
                for (int j = 0; j < 4; j++)
                    mma_f16(acc[i * 4 + j], af[i], bf[j][0], bf[j][1]);
        }
    }

    // ---- Epilogue ----
#pragma unroll
    for (int i = 0; i < 4; i++) {
#pragma unroll
        for (int j = 0; j < 4; j++) {
            const float* d = acc[i * 4 + j];
            int col = bn + wn + j * 8 + 2 * tig;
            float2 b2 = *(const float2*)(bias + col);
            int row_lo = bm + wm + i * 16 + g;
            int row_hi = row_lo + 8;
            float2 vlo = { (d[0] + b2.x) * oscale, (d[1] + b2.y) * oscale };
            float2 vhi = { (d[2] + b2.x) * oscale, (d[3] + b2.y) * oscale };
            if (mode == 0) {
                float* of = (float*)out;
                *(float2*)(of + (size_t)row_lo * D_ + col) = vlo;
                *(float2*)(of + (size_t)row_hi * D_ + col) = vhi;
            } else {
                __half* oh = (__half*)out;
                int h = col / HD_, dd = col % HD_;
                int b0i = row_lo / S_, s0 = row_lo % S_;
                int b1i = row_hi / S_, s1 = row_hi % S_;
                *(__half2*)(oh + ((size_t)((b0i * H_ + h) * S_ + s0)) * HD_ + dd)
                    = __floats2half2_rn(vlo.x, vlo.y);
                *(__half2*)(oh + ((size_t)((b1i * H_ + h) * S_ + s1)) * HD_ + dd)
                    = __floats2half2_rn(vhi.x, vhi.y);
            }
        }
    }
}

// ---------------------------------------------------------------------------
// Flash attention fp16 (R15 pipeline) with BASE-2 softmax:
// Q pre-scaled by 0.125*log2e -> scores in log2 domain; exp = raw ex2.approx.
// K and V double-buffered, one sync per KV tile.
// ---------------------------------------------------------------------------
#define AKV 64
#define AQ  64
#define KSTR 72

__global__ void __launch_bounds__(128, 4) attn_kernel(
    const __half* __restrict__ Qb, const __half* __restrict__ Kb,
    const __half* __restrict__ Vb, __half* __restrict__ Ob)
{
    __shared__ __half Ks0[64 * KSTR];
    __shared__ __half Ks1[64 * KSTR];
    __shared__ __half Vs0[64 * KSTR];
    __shared__ __half Vs1[64 * KSTR];

    const int bh   = blockIdx.y;
    const int qt   = blockIdx.x;
    const int tid  = threadIdx.x;
    const int warp = tid >> 5;
    const int lane = tid & 31;
    const int g    = lane >> 2;
    const int tig  = lane & 3;

    const int b_r = (lane & 7) + ((lane >> 4) & 1) * 8;
    const int b_c = ((lane >> 3) & 1) * 8;
    const int kb_r = (lane & 7) + ((lane >> 3) & 1) * 8;
    const int kb_n = (lane >> 4) * 8;

    const __half* Kbase = Kb + (size_t)bh * S_ * HD_;
    const __half* Vbase = Vb + (size_t)bh * S_ * HD_;

    // Prologue: tile 0 K+V into buffer 0
    {
#pragma unroll
        for (int i = 0; i < 4; i++) {
            int idx = i * 128 + tid;
            int r = idx >> 3, seg = idx & 7;
            cp_async16((char*)Ks0 + r * (KSTR * 2) + seg * 16,
                       Kbase + (size_t)r * HD_ + seg * 8);
            cp_async16((char*)Vs0 + r * (KSTR * 2) + seg * 16,
                       Vbase + (size_t)r * HD_ + seg * 8);
        }
        asm volatile("cp.async.commit_group;");
    }

    const int qrow0 = qt * AQ + warp * 16;
    const __half* Qp = Qb + ((size_t)bh * S_ + qrow0) * HD_;
    unsigned qa[4][4];
#pragma unroll
    for (int kc = 0; kc < 4; kc++) {
        int kh = kc * 16;
        qa[kc][0] = *(const unsigned*)(Qp + (size_t)g * HD_ + kh + 2 * tig);
        qa[kc][1] = *(const unsigned*)(Qp + (size_t)(g + 8) * HD_ + kh + 2 * tig);
        qa[kc][2] = *(const unsigned*)(Qp + (size_t)g * HD_ + kh + 8 + 2 * tig);
        qa[kc][3] = *(const unsigned*)(Qp + (size_t)(g + 8) * HD_ + kh + 8 + 2 * tig);
    }

    const uint32_t ks0b = smem_u32(Ks0) + (uint32_t)((b_r * KSTR + b_c) * 2);
    const uint32_t ks1b = smem_u32(Ks1) + (uint32_t)((b_r * KSTR + b_c) * 2);
    const uint32_t vs0b = smem_u32(Vs0) + (uint32_t)((kb_r * KSTR + kb_n) * 2);
    const uint32_t vs1b = smem_u32(Vs1) + (uint32_t)((kb_r * KSTR + kb_n) * 2);

    float o[8][4];
#pragma unroll
    for (int j = 0; j < 8; j++)
#pragma unroll
        for (int e = 0; e < 4; e++) o[j][e] = 0.0f;
    float m_lo = -1e30f, m_hi = -1e30f;
    float l_lo = 0.0f,   l_hi = 0.0f;
    const unsigned FULL = 0xffffffffu;

    const int NT = S_ / AKV;
    for (int kt = 0; kt < NT; kt++) {
        asm volatile("cp.async.wait_group 0;");
        __syncthreads();

        if (kt + 1 < NT) {
            __half* Kd = ((kt + 1) & 1) ? Ks1 : Ks0;
            __half* Vd = ((kt + 1) & 1) ? Vs1 : Vs0;
            const __half* Kp = Kbase + (size_t)(kt + 1) * AKV * HD_;
            const __half* Vp = Vbase + (size_t)(kt + 1) * AKV * HD_;
#pragma unroll
            for (int i = 0; i < 4; i++) {
                int idx = i * 128 + tid;
                int r = idx >> 3, seg = idx & 7;
                cp_async16((char*)Kd + r * (KSTR * 2) + seg * 16,
                           Kp + (size_t)r * HD_ + seg * 8);
                cp_async16((char*)Vd + r * (KSTR * 2) + seg * 16,
                           Vp + (size_t)r * HD_ + seg * 8);
            }
            asm volatile("cp.async.commit_group;");
        }

        const uint32_t ksb = (kt & 1) ? ks1b : ks0b;
        const uint32_t vsb = (kt & 1) ? vs1b : vs0b;

        // ---- S = Q @ K^T (scores already in log2 domain) ----
        float s[8][4];
#pragma unroll
        for (int j = 0; j < 8; j++)
#pragma unroll
            for (int e = 0; e < 4; e++) s[j][e] = 0.0f;

#pragma unroll
        for (int kc = 0; kc < 4; kc++) {
            uint32_t ka = ksb + kc * 32;
#pragma unroll
            for (int jp = 0; jp < 4; jp++) {
                unsigned b00, b01, b10, b11;
                ldsm_x4(b00, b01, b10, b11, ka + jp * 16 * KSTR * 2);
                mma_f16(s[2 * jp],     qa[kc], b00, b01);
                mma_f16(s[2 * jp + 1], qa[kc], b10, b11);
            }
        }

        // ---- Online softmax (base-2) ----
        float mx_lo = -1e30f, mx_hi = -1e30f;
#pragma unroll
        for (int j = 0; j < 8; j++) {
            mx_lo = fmaxf(mx_lo, fmaxf(s[j][0], s[j][1]));
            mx_hi = fmaxf(mx_hi, fmaxf(s[j][2], s[j][3]));
        }
        mx_lo = fmaxf(mx_lo, __shfl_xor_sync(FULL, mx_lo, 1));
        mx_lo = fmaxf(mx_lo, __shfl_xor_sync(FULL, mx_lo, 2));
        mx_hi = fmaxf(mx_hi, __shfl_xor_sync(FULL, mx_hi, 1));
        mx_hi = fmaxf(mx_hi, __shfl_xor_sync(FULL, mx_hi, 2));

        float mn_lo = fmaxf(m_lo, mx_lo);
        float mn_hi = fmaxf(m_hi, mx_hi);
        float al_lo = ex2f(m_lo - mn_lo);
        float al_hi = ex2f(m_hi - mn_hi);
        m_lo = mn_lo; m_hi = mn_hi;

        float sum_lo = 0.0f, sum_hi = 0.0f;
#pragma unroll
        for (int j = 0; j < 8; j++) {
            float p0 = ex2f(s[j][0] - mn_lo);
            float p1 = ex2f(s[j][1] - mn_lo);
            float p2 = ex2f(s[j][2] - mn_hi);
            float p3 = ex2f(s[j][3] - mn_hi);
            sum_lo += p0 + p1;
            sum_hi += p2 + p3;
            s[j][0] = p0; s[j][1] = p1; s[j][2] = p2; s[j][3] = p3;
        }
        sum_lo += __shfl_xor_sync(FULL, sum_lo, 1);
        sum_lo += __shfl_xor_sync(FULL, sum_lo, 2);
        sum_hi += __shfl_xor_sync(FULL, sum_hi, 1);
        sum_hi += __shfl_xor_sync(FULL, sum_hi, 2);
        l_lo = l_lo * al_lo + sum_lo;
        l_hi = l_hi * al_hi + sum_hi;

#pragma unroll
        for (int j = 0; j < 8; j++) {
            o[j][0] *= al_lo; o[j][1] *= al_lo;
            o[j][2] *= al_hi; o[j][3] *= al_hi;
        }

        // ---- O += P @ V ----
#pragma unroll
        for (int kc = 0; kc < 4; kc++) {
            unsigned pa[4];
            pa[0] = pack_h2(s[2 * kc][0],     s[2 * kc][1]);
            pa[1] = pack_h2(s[2 * kc][2],     s[2 * kc][3]);
            pa[2] = pack_h2(s[2 * kc + 1][0], s[2 * kc + 1][1]);
            pa[3] = pack_h2(s[2 * kc + 1][2], s[2 * kc + 1][3]);
            uint32_t ka = vsb + kc * 16 * KSTR * 2;
#pragma unroll
            for (int jp = 0; jp < 4; jp++) {
                unsigned b00, b01, b10, b11;
                ldsm_x4_t(b00, b01, b10, b11, ka + jp * 32);
                mma_f16(o[2 * jp],     pa, b00, b01);
                mma_f16(o[2 * jp + 1], pa, b10, b11);
            }
        }
        // next iteration's top sync covers buffer reuse
    }

    // ---- Normalize + write fp16 to [B,S,D] ----
    float inv_lo = 1.0f / l_lo;
    float inv_hi = 1.0f / l_hi;
    int b = bh / H_, h = bh % H_;
    __half* orow_lo = Ob + ((size_t)(b * S_ + qrow0 + g)) * D_ + h * HD_;
    __half* orow_hi = Ob + ((size_t)(b * S_ + qrow0 + g + 8)) * D_ + h * HD_;
#pragma unroll
    for (int jn = 0; jn < 8; jn++) {
        *(__half2*)(orow_lo + jn * 8 + 2 * tig)
            = __floats2half2_rn(o[jn][0] * inv_lo, o[jn][1] * inv_lo);
        *(__half2*)(orow_hi + jn * 8 + 2 * tig)
            = __floats2half2_rn(o[jn][2] * inv_hi, o[jn][3] * inv_hi);
    }
}

// ---------------------------------------------------------------------------
// Launch
// ---------------------------------------------------------------------------
extern "C" void kernel_launch(void* const* d_in, const int* in_sizes, int n_in,
                              void* d_out, int out_size)
{
    (void)in_sizes; (void)n_in; (void)out_size;
    const float* x  = (const float*)d_in[0];
    const float* Wq = (const float*)d_in[1];
    const float* bq = (const float*)d_in[2];
    const float* Wk = (const float*)d_in[3];
    const float* bk = (const float*)d_in[4];
    const float* Wv = (const float*)d_in[5];
    const float* bv = (const float*)d_in[6];
    const float* Wo = (const float*)d_in[7];
    const float* bo = (const float*)d_in[8];
    float* out = (float*)d_out;

    void *pq, *pk, *pv, *patt, *pxt, *pwt;
    cudaGetSymbolAddress(&pq, g_q);
    cudaGetSymbolAddress(&pk, g_k);
    cudaGetSymbolAddress(&pv, g_v);
    cudaGetSymbolAddress(&patt, g_att);
    cudaGetSymbolAddress(&pxt, g_xt);
    cudaGetSymbolAddress(&pwt, g_wt);
    __half* qb = (__half*)pq;
    __half* kb = (__half*)pk;
    __half* vb = (__half*)pv;
    __half* ab = (__half*)patt;
    __half* xt = (__half*)pxt;
    __half* wt = (__half*)pwt;

    cudaFuncSetAttribute(gemm_f16_kernel,
                         cudaFuncAttributeMaxDynamicSharedMemorySize, GSMB);

    // 1) Prep
    int nthr = XN4 + 4 * WN4;
    cvt_all_kernel<<<nthr / 256, 256>>>(x, Wq, Wk, Wv, Wo, xt, wt);

    // 2) QKV projections (Q scaled by log2e/sqrt(HD) for base-2 softmax)
    const float QSCALE = 0.125f * 1.4426950408889634f;
    dim3 ggrid(D_ / 128, M_TOT / 128);            // (8, 32)
    gemm_f16_kernel<<<ggrid, 256, GSMB>>>(xt, wt + 0 * (size_t)D_ * D_, bq, qb, 1, QSCALE);
    gemm_f16_kernel<<<ggrid, 256, GSMB>>>(xt, wt + 1 * (size_t)D_ * D_, bk, kb, 1, 1.0f);
    gemm_f16_kernel<<<ggrid, 256, GSMB>>>(xt, wt + 2 * (size_t)D_ * D_, bv, vb, 1, 1.0f);

    // 3) Attention
    dim3 agrid(S_ / AQ, B_ * H_);                 // (32, 32)
    attn_kernel<<<agrid, 128>>>(qb, kb, vb, ab);

    // 4) Output projection
    gemm_f16_kernel<<<ggrid, 256, GSMB>>>(ab, wt + 3 * (size_t)D_ * D_, bo, out, 0, 1.0f);
}

// round 17
// speedup vs baseline: 1.1170x; 1.0197x over previous
#include <cuda_runtime.h>
#include <cuda_fp16.h>
#include <cstdint>

// Problem constants (fixed shapes)
#define B_   2
#define S_   2048
#define D_   1024
#define H_   16
#define HD_  64
#define M_TOT (B_ * S_)   // 4096

// ---------------------------------------------------------------------------
// Scratch buffers (fp16; Q pre-scaled by log2e/sqrt(HD); natural layouts)
// ---------------------------------------------------------------------------
__device__ __half g_q[B_ * H_ * S_ * HD_];    // [B,H,S,HD]
__device__ __half g_k[B_ * H_ * S_ * HD_];    // [B,H,S,HD]
__device__ __half g_v[B_ * H_ * S_ * HD_];    // [B,H,S,HD]
__device__ __half g_att[B_ * S_ * D_];        // [B,S,D]
__device__ __half g_xt[M_TOT * D_];           // x fp16 [M,K]
__device__ __half g_wt[4 * D_ * D_];          // W fp16 [K,N] x4 (natural)

// ---------------------------------------------------------------------------
// Helpers
// ---------------------------------------------------------------------------
__device__ __forceinline__ void mma_f16(float* d, const unsigned* a,
                                        unsigned b0, unsigned b1) {
    asm volatile(
        "mma.sync.aligned.m16n8k16.row.col.f32.f16.f16.f32 "
        "{%0,%1,%2,%3}, {%4,%5,%6,%7}, {%8,%9}, {%0,%1,%2,%3};"
        : "+f"(d[0]), "+f"(d[1]), "+f"(d[2]), "+f"(d[3])
        : "r"(a[0]), "r"(a[1]), "r"(a[2]), "r"(a[3]), "r"(b0), "r"(b1));
}

__device__ __forceinline__ void cp_async16(void* smem_dst, const void* gmem_src) {
    unsigned saddr = (unsigned)__cvta_generic_to_shared(smem_dst);
    asm volatile("cp.async.cg.shared.global [%0], [%1], 16;"
                 :: "r"(saddr), "l"(gmem_src));
}

__device__ __forceinline__ float ex2f(float x) {
    float y;
    asm("ex2.approx.f32 %0, %1;" : "=f"(y) : "f"(x));
    return y;
}

// Packed two-lane exp2 on fp16 pair; input/output are half2 bit patterns.
__device__ __forceinline__ unsigned ex2h2(unsigned x) {
    unsigned y;
    asm("ex2.approx.f16x2 %0, %1;" : "=r"(y) : "r"(x));
    return y;
}

__device__ __forceinline__ unsigned pack_h2f(float lo, float hi) {
    __half2 h = __floats2half2_rn(lo, hi);
    return *reinterpret_cast<unsigned*>(&h);
}

__device__ __forceinline__ float2 h2_to_f2(unsigned u) {
    __half2 h = *reinterpret_cast<__half2*>(&u);
    return __half22float2(h);
}

__device__ __forceinline__ void ldsm_x4(unsigned& d0, unsigned& d1,
                                        unsigned& d2, unsigned& d3,
                                        uint32_t addr) {
    asm volatile("ldmatrix.sync.aligned.m8n8.x4.shared.b16 {%0,%1,%2,%3}, [%4];"
                 : "=r"(d0), "=r"(d1), "=r"(d2), "=r"(d3) : "r"(addr));
}

__device__ __forceinline__ void ldsm_x4_t(unsigned& d0, unsigned& d1,
                                          unsigned& d2, unsigned& d3,
                                          uint32_t addr) {
    asm volatile("ldmatrix.sync.aligned.m8n8.x4.trans.shared.b16 {%0,%1,%2,%3}, [%4];"
                 : "=r"(d0), "=r"(d1), "=r"(d2), "=r"(d3) : "r"(addr));
}

__device__ __forceinline__ uint32_t smem_u32(const void* p) {
    return (uint32_t)__cvta_generic_to_shared(p);
}

// ---------------------------------------------------------------------------
// Prep: x AND all W -> fp16 (pure elementwise, one kernel)
// ---------------------------------------------------------------------------
#define XN4 (M_TOT * D_ / 4)       // 1048576
#define WN4 (D_ * D_ / 4)          // 262144 each

__global__ void __launch_bounds__(256) cvt_all_kernel(
    const float* __restrict__ x,
    const float* __restrict__ wq, const float* __restrict__ wk,
    const float* __restrict__ wv, const float* __restrict__ wo,
    __half* __restrict__ xt, __half* __restrict__ wt)
{
    int i = blockIdx.x * 256 + threadIdx.x;
    const float4* s;
    __half2* d;
    if (i < XN4) {
        s = (const float4*)x + i;
        d = (__half2*)xt + 2 * i;
    } else {
        int j = i - XN4;
        int w = j >> 18;
        int off = j & (WN4 - 1);
        const float* ws = (w == 0) ? wq : (w == 1) ? wk : (w == 2) ? wv : wo;
        s = (const float4*)ws + off;
        d = (__half2*)(wt + (size_t)w * D_ * D_) + 2 * off;
    }
    float4 v = *s;
    d[0] = __floats2half2_rn(v.x, v.y);
    d[1] = __floats2half2_rn(v.z, v.w);
}

// ---------------------------------------------------------------------------
// FP16 GEMM (frozen): out = A[M,K] @ W[K,N] + bias, N=D_ compile-time.
// mode 0: fp32 [M,N]; mode 1: fp16 scatter [B,H,S,HD].
// ---------------------------------------------------------------------------
#define GSTR 72
#define BSTR 136
#define ABYT (128 * GSTR * 2)
#define BBYT (64 * BSTR * 2)
#define STAGEB (ABYT + BBYT)
#define GSMB (3 * STAGEB)

extern __shared__ char tsm[];

#define GEMM_ISSUE(t)                                                        \
    do {                                                                     \
        char* sbase = tsm + ((t) % 3) * STAGEB;                              \
        _Pragma("unroll")                                                    \
        for (int ii = 0; ii < 4; ii++) {                                     \
            int idx = ii * 256 + tid;                                        \
            int ra = idx >> 3, sa = idx & 7;                                 \
            cp_async16(sbase + ra * (GSTR * 2) + sa * 16,                    \
                       Ag + (size_t)ra * D_ + (t) * 64 + sa * 8);            \
            int rb = idx >> 4, sg = idx & 15;                                \
            cp_async16(sbase + ABYT + rb * (BSTR * 2) + sg * 16,             \
                       Bg + (size_t)((t) * 64 + rb) * D_ + sg * 8);          \
        }                                                                    \
        asm volatile("cp.async.commit_group;");                              \
    } while (0)

__global__ void __launch_bounds__(256, 2) gemm_f16_kernel(
    const __half* __restrict__ A, const __half* __restrict__ W,
    const float* __restrict__ bias, void* __restrict__ out,
    int mode, float oscale)
{
    const int tid  = threadIdx.x;
    const int warp = tid >> 5;
    const int lane = tid & 31;
    const int g    = lane >> 2;
    const int tig  = lane & 3;
    const int wm   = (warp >> 2) * 64;
    const int wn   = (warp & 3) * 32;
    const int bm   = blockIdx.y * 128;
    const int bn   = blockIdx.x * 128;

    const __half* Ag = A + (size_t)bm * D_;
    const __half* Bg = W + bn;

    const int a_r = (lane & 7) + ((lane >> 3) & 1) * 8;
    const int a_c = (lane >> 4) * 8;
    const int kb_r = (lane & 7) + ((lane >> 3) & 1) * 8;
    const int kb_n = (lane >> 4) * 8;

    float acc[16][4];
#pragma unroll
    for (int f = 0; f < 16; f++)
#pragma unroll
        for (int e = 0; e < 4; e++) acc[f][e] = 0.0f;

    const uint32_t sb = smem_u32(tsm);
    const int NT = D_ / 64;
    GEMM_ISSUE(0);
    GEMM_ISSUE(1);

    for (int t = 0; t < NT; t++) {
        if (t < NT - 1) asm volatile("cp.async.wait_group 1;");
        else            asm volatile("cp.async.wait_group 0;");
        __syncthreads();

        if (t + 2 < NT) GEMM_ISSUE(t + 2);

        uint32_t abase = sb + (t % 3) * STAGEB
                       + (uint32_t)(((wm + a_r) * GSTR + a_c) * 2);
        uint32_t bbase = sb + (t % 3) * STAGEB + ABYT
                       + (uint32_t)((kb_r * BSTR + wn + kb_n) * 2);

#pragma unroll
        for (int ks = 0; ks < 4; ks++) {
            unsigned af[4][4];
#pragma unroll
            for (int i = 0; i < 4; i++)
                ldsm_x4(af[i][0], af[i][1], af[i][2], af[i][3],
                        abase + ks * 32 + i * 16 * GSTR * 2);
            unsigned bf[4][2];
#pragma unroll
            for (int jp = 0; jp < 2; jp++)
                ldsm_x4_t(bf[2 * jp][0], bf[2 * jp][1],
                          bf[2 * jp + 1][0], bf[2 * jp + 1][1],
                          bbase + ks * 16 * BSTR * 2 + jp * 32);
#pragma unroll
            for (int i = 0; i < 4; i++)
#pragma unroll
                for (int j = 0; j < 4; j++)
                    mma_f16(acc[i * 4 + j], af[i], bf[j][0], bf[j][1]);
        }
    }

    // ---- Epilogue ----
#pragma unroll
    for (int i = 0; i < 4; i++) {
#pragma unroll
        for (int j = 0; j < 4; j++) {
            const float* d = acc[i * 4 + j];
            int col = bn + wn + j * 8 + 2 * tig;
            float2 b2 = *(const float2*)(bias + col);
            int row_lo = bm + wm + i * 16 + g;
            int row_hi = row_lo + 8;
            float2 vlo = { (d[0] + b2.x) * oscale, (d[1] + b2.y) * oscale };
            float2 vhi = { (d[2] + b2.x) * oscale, (d[3] + b2.y) * oscale };
            if (mode == 0) {
                float* of = (float*)out;
                *(float2*)(of + (size_t)row_lo * D_ + col) = vlo;
                *(float2*)(of + (size_t)row_hi * D_ + col) = vhi;
            } else {
                __half* oh = (__half*)out;
                int h = col / HD_, dd = col % HD_;
                int b0i = row_lo / S_, s0 = row_lo % S_;
                int b1i = row_hi / S_, s1 = row_hi % S_;
                *(__half2*)(oh + ((size_t)((b0i * H_ + h) * S_ + s0)) * HD_ + dd)
                    = __floats2half2_rn(vlo.x, vlo.y);
                *(__half2*)(oh + ((size_t)((b1i * H_ + h) * S_ + s1)) * HD_ + dd)
                    = __floats2half2_rn(vhi.x, vhi.y);
            }
        }
    }
}

// ---------------------------------------------------------------------------
// Flash attention fp16, base-2 softmax with PACKED f16x2 exp (half the MUFU
// ops; exp output IS the PV A-fragment). K+V double-buffered, one sync/tile.
// ---------------------------------------------------------------------------
#define AKV 64
#define AQ  64
#define KSTR 72

__global__ void __launch_bounds__(128, 4) attn_kernel(
    const __half* __restrict__ Qb, const __half* __restrict__ Kb,
    const __half* __restrict__ Vb, __half* __restrict__ Ob)
{
    __shared__ __half Ks0[64 * KSTR];
    __shared__ __half Ks1[64 * KSTR];
    __shared__ __half Vs0[64 * KSTR];
    __shared__ __half Vs1[64 * KSTR];

    const int bh   = blockIdx.y;
    const int qt   = blockIdx.x;
    const int tid  = threadIdx.x;
    const int warp = tid >> 5;
    const int lane = tid & 31;
    const int g    = lane >> 2;
    const int tig  = lane & 3;

    const int b_r = (lane & 7) + ((lane >> 4) & 1) * 8;
    const int b_c = ((lane >> 3) & 1) * 8;
    const int kb_r = (lane & 7) + ((lane >> 3) & 1) * 8;
    const int kb_n = (lane >> 4) * 8;

    const __half* Kbase = Kb + (size_t)bh * S_ * HD_;
    const __half* Vbase = Vb + (size_t)bh * S_ * HD_;

    // Prologue: tile 0 K+V into buffer 0
    {
#pragma unroll
        for (int i = 0; i < 4; i++) {
            int idx = i * 128 + tid;
            int r = idx >> 3, seg = idx & 7;
            cp_async16((char*)Ks0 + r * (KSTR * 2) + seg * 16,
                       Kbase + (size_t)r * HD_ + seg * 8);
            cp_async16((char*)Vs0 + r * (KSTR * 2) + seg * 16,
                       Vbase + (size_t)r * HD_ + seg * 8);
        }
        asm volatile("cp.async.commit_group;");
    }

    const int qrow0 = qt * AQ + warp * 16;
    const __half* Qp = Qb + ((size_t)bh * S_ + qrow0) * HD_;
    unsigned qa[4][4];
#pragma unroll
    for (int kc = 0; kc < 4; kc++) {
        int kh = kc * 16;
        qa[kc][0] = *(const unsigned*)(Qp + (size_t)g * HD_ + kh + 2 * tig);
        qa[kc][1] = *(const unsigned*)(Qp + (size_t)(g + 8) * HD_ + kh + 2 * tig);
        qa[kc][2] = *(const unsigned*)(Qp + (size_t)g * HD_ + kh + 8 + 2 * tig);
        qa[kc][3] = *(const unsigned*)(Qp + (size_t)(g + 8) * HD_ + kh + 8 + 2 * tig);
    }

    const uint32_t ks0b = smem_u32(Ks0) + (uint32_t)((b_r * KSTR + b_c) * 2);
    const uint32_t ks1b = smem_u32(Ks1) + (uint32_t)((b_r * KSTR + b_c) * 2);
    const uint32_t vs0b = smem_u32(Vs0) + (uint32_t)((kb_r * KSTR + kb_n) * 2);
    const uint32_t vs1b = smem_u32(Vs1) + (uint32_t)((kb_r * KSTR + kb_n) * 2);

    float o[8][4];
#pragma unroll
    for (int j = 0; j < 8; j++)
#pragma unroll
        for (int e = 0; e < 4; e++) o[j][e] = 0.0f;
    float m_lo = -1e30f, m_hi = -1e30f;
    float l_lo = 0.0f,   l_hi = 0.0f;
    const unsigned FULL = 0xffffffffu;

    const int NT = S_ / AKV;
    for (int kt = 0; kt < NT; kt++) {
        asm volatile("cp.async.wait_group 0;");
        __syncthreads();

        if (kt + 1 < NT) {
            __half* Kd = ((kt + 1) & 1) ? Ks1 : Ks0;
            __half* Vd = ((kt + 1) & 1) ? Vs1 : Vs0;
            const __half* Kp = Kbase + (size_t)(kt + 1) * AKV * HD_;
            const __half* Vp = Vbase + (size_t)(kt + 1) * AKV * HD_;
#pragma unroll
            for (int i = 0; i < 4; i++) {
                int idx = i * 128 + tid;
                int r = idx >> 3, seg = idx & 7;
                cp_async16((char*)Kd + r * (KSTR * 2) + seg * 16,
                           Kp + (size_t)r * HD_ + seg * 8);
                cp_async16((char*)Vd + r * (KSTR * 2) + seg * 16,
                           Vp + (size_t)r * HD_ + seg * 8);
            }
            asm volatile("cp.async.commit_group;");
        }

        const uint32_t ksb = (kt & 1) ? ks1b : ks0b;
        const uint32_t vsb = (kt & 1) ? vs1b : vs0b;

        // ---- S = Q @ K^T (log2-domain scores) ----
        float s[8][4];
#pragma unroll
        for (int j = 0; j < 8; j++)
#pragma unroll
            for (int e = 0; e < 4; e++) s[j][e] = 0.0f;

#pragma unroll
        for (int kc = 0; kc < 4; kc++) {
            uint32_t ka = ksb + kc * 32;
#pragma unroll
            for (int jp = 0; jp < 4; jp++) {
                unsigned b00, b01, b10, b11;
                ldsm_x4(b00, b01, b10, b11, ka + jp * 16 * KSTR * 2);
                mma_f16(s[2 * jp],     qa[kc], b00, b01);
                mma_f16(s[2 * jp + 1], qa[kc], b10, b11);
            }
        }

        // ---- Online softmax (base-2, packed fp16 exp) ----
        float mx_lo = -1e30f, mx_hi = -1e30f;
#pragma unroll
        for (int j = 0; j < 8; j++) {
            mx_lo = fmaxf(mx_lo, fmaxf(s[j][0], s[j][1]));
            mx_hi = fmaxf(mx_hi, fmaxf(s[j][2], s[j][3]));
        }
        mx_lo = fmaxf(mx_lo, __shfl_xor_sync(FULL, mx_lo, 1));
        mx_lo = fmaxf(mx_lo, __shfl_xor_sync(FULL, mx_lo, 2));
        mx_hi = fmaxf(mx_hi, __shfl_xor_sync(FULL, mx_hi, 1));
        mx_hi = fmaxf(mx_hi, __shfl_xor_sync(FULL, mx_hi, 2));

        float mn_lo = fmaxf(m_lo, mx_lo);
        float mn_hi = fmaxf(m_hi, mx_hi);
        float al_lo = ex2f(m_lo - mn_lo);
        float al_hi = ex2f(m_hi - mn_hi);
        m_lo = mn_lo; m_hi = mn_hi;

        // ps[j][0] = exp2 of (row-lo c0,c1) packed; ps[j][1] = (row-hi c0,c1)
        unsigned ps[8][2];
        float sum_lo = 0.0f, sum_hi = 0.0f;
#pragma unroll
        for (int j = 0; j < 8; j++) {
            unsigned hlo = pack_h2f(s[j][0] - mn_lo, s[j][1] - mn_lo);
            unsigned hhi = pack_h2f(s[j][2] - mn_hi, s[j][3] - mn_hi);
            ps[j][0] = ex2h2(hlo);
            ps[j][1] = ex2h2(hhi);
            float2 flo = h2_to_f2(ps[j][0]);
            float2 fhi = h2_to_f2(ps[j][1]);
            sum_lo += flo.x + flo.y;
            sum_hi += fhi.x + fhi.y;
        }
        sum_lo += __shfl_xor_sync(FULL, sum_lo, 1);
        sum_lo += __shfl_xor_sync(FULL, sum_lo, 2);
        sum_hi += __shfl_xor_sync(FULL, sum_hi, 1);
        sum_hi += __shfl_xor_sync(FULL, sum_hi, 2);
        l_lo = l_lo * al_lo + sum_lo;
        l_hi = l_hi * al_hi + sum_hi;

#pragma unroll
        for (int j = 0; j < 8; j++) {
            o[j][0] *= al_lo; o[j][1] *= al_lo;
            o[j][2] *= al_hi; o[j][3] *= al_hi;
        }

        // ---- O += P @ V  (ps registers ARE the A fragments) ----
#pragma unroll
        for (int kc = 0; kc < 4; kc++) {
            unsigned pa[4];
            pa[0] = ps[2 * kc][0];
            pa[1] = ps[2 * kc][1];
            pa[2] = ps[2 * kc + 1][0];
            pa[3] = ps[2 * kc + 1][1];
            uint32_t ka = vsb + kc * 16 * KSTR * 2;
#pragma unroll
            for (int jp = 0; jp < 4; jp++) {
                unsigned b00, b01, b10, b11;
                ldsm_x4_t(b00, b01, b10, b11, ka + jp * 32);
                mma_f16(o[2 * jp],     pa, b00, b01);
                mma_f16(o[2 * jp + 1], pa, b10, b11);
            }
        }
        // next iteration's top sync covers buffer reuse
    }

    // ---- Normalize + write fp16 to [B,S,D] ----
    float inv_lo = 1.0f / l_lo;
    float inv_hi = 1.0f / l_hi;
    int b = bh / H_, h = bh % H_;
    __half* orow_lo = Ob + ((size_t)(b * S_ + qrow0 + g)) * D_ + h * HD_;
    __half* orow_hi = Ob + ((size_t)(b * S_ + qrow0 + g + 8)) * D_ + h * HD_;
#pragma unroll
    for (int jn = 0; jn < 8; jn++) {
        *(__half2*)(orow_lo + jn * 8 + 2 * tig)
            = __floats2half2_rn(o[jn][0] * inv_lo, o[jn][1] * inv_lo);
        *(__half2*)(orow_hi + jn * 8 + 2 * tig)
            = __floats2half2_rn(o[jn][2] * inv_hi, o[jn][3] * inv_hi);
    }
}

// ---------------------------------------------------------------------------
// Launch
// ---------------------------------------------------------------------------
extern "C" void kernel_launch(void* const* d_in, const int* in_sizes, int n_in,
                              void* d_out, int out_size)
{
    (void)in_sizes; (void)n_in; (void)out_size;
    const float* x  = (const float*)d_in[0];
    const float* Wq = (const float*)d_in[1];
    const float* bq = (const float*)d_in[2];
    const float* Wk = (const float*)d_in[3];
    const float* bk = (const float*)d_in[4];
    const float* Wv = (const float*)d_in[5];
    const float* bv = (const float*)d_in[6];
    const float* Wo = (const float*)d_in[7];
    const float* bo = (const float*)d_in[8];
    float* out = (float*)d_out;

    void *pq, *pk, *pv, *patt, *pxt, *pwt;
    cudaGetSymbolAddress(&pq, g_q);
    cudaGetSymbolAddress(&pk, g_k);
    cudaGetSymbolAddress(&pv, g_v);
    cudaGetSymbolAddress(&patt, g_att);
    cudaGetSymbolAddress(&pxt, g_xt);
    cudaGetSymbolAddress(&pwt, g_wt);
    __half* qb = (__half*)pq;
    __half* kb = (__half*)pk;
    __half* vb = (__half*)pv;
    __half* ab = (__half*)patt;
    __half* xt = (__half*)pxt;
    __half* wt = (__half*)pwt;

    cudaFuncSetAttribute(gemm_f16_kernel,
                         cudaFuncAttributeMaxDynamicSharedMemorySize, GSMB);

    // 1) Prep
    int nthr = XN4 + 4 * WN4;
    cvt_all_kernel<<<nthr / 256, 256>>>(x, Wq, Wk, Wv, Wo, xt, wt);

    // 2) QKV projections (Q scaled by log2e/sqrt(HD) for base-2 softmax)
    const float QSCALE = 0.125f * 1.4426950408889634f;
    dim3 ggrid(D_ / 128, M_TOT / 128);            // (8, 32)
    gemm_f16_kernel<<<ggrid, 256, GSMB>>>(xt, wt + 0 * (size_t)D_ * D_, bq, qb, 1, QSCALE);
    gemm_f16_kernel<<<ggrid, 256, GSMB>>>(xt, wt + 1 * (size_t)D_ * D_, bk, kb, 1, 1.0f);
    gemm_f16_kernel<<<ggrid, 256, GSMB>>>(xt, wt + 2 * (size_t)D_ * D_, bv, vb, 1, 1.0f);

    // 3) Attention
    dim3 agrid(S_ / AQ, B_ * H_);                 // (32, 32)
    attn_kernel<<<agrid, 128>>>(qb, kb, vb, ab);

    // 4) Output projection
    gemm_f16_kernel<<<ggrid, 256, GSMB>>>(ab, wt + 3 * (size_t)D_ * D_, bo, out, 0, 1.0f);
}